// round 8
// baseline (speedup 1.0000x reference)
#include <cuda_runtime.h>

#define BB 512
#define TT 512
#define NS 64

// sm_103a packed fp32 pipe: 2 full-precision fp32 FMAs / MULs / ADDs per instr
#define FMA2(acc, p, e) \
    asm("fma.rn.f32x2 %0, %1, %2, %0;" : "+l"(acc) : "l"(p), "l"(e))
#define MUL2(out, a, b) \
    asm("mul.rn.f32x2 %0, %1, %2;" : "=l"(out) : "l"(a), "l"(b))
#define ADD2(out, a, b) \
    asm("add.rn.f32x2 %0, %1, %2;" : "=l"(out) : "l"(a), "l"(b))
#define UNPACK2(lo, hi, v) \
    asm("mov.b64 {%0, %1}, %2;" : "=r"(lo), "=r"(hi) : "l"(v))

__device__ int d_perm[BB];

// Rank batches by sequence length (descending): longest chains first.
__global__ void rank_kernel(const int* __restrict__ lens) {
    __shared__ int L[BB];
    const int b = threadIdx.x;
    L[b] = lens[b];
    __syncthreads();
    const int myl = L[b];
    int r = 0;
    #pragma unroll 8
    for (int i = 0; i < BB; ++i) {
        const int li = L[i];
        r += (li > myl) || (li == myl && i < b);
    }
    d_perm[r] = b;
}

// 96 threads = 2 chain warps (thread j owns state j, full 64-wide FMA2 dot)
// + 1 producer warp feeding pe = exp(emit) through an 8-slot smem ring,
// 6 steps ahead. One plain __syncthreads per step, shared by all 3 warps.
__global__ __launch_bounds__(96) void crf_kernel(
    const float* __restrict__ inputs,   // [B,T,N]
    const float* __restrict__ trans,    // [N,N]
    const int*   __restrict__ tags,    // [B,T]
    const int*   __restrict__ lens,    // [B]
    float*       __restrict__ out,     // [B] ll, then [N*N] trans copy
    int write_trans)
{
    const int bb   = blockIdx.x;
    const int b    = d_perm[bb];
    const int tid  = threadIdx.x;
    const int j    = tid;           // state index for consumers (tid < 64)
    const int w    = tid >> 5;      // warp: 0,1 = chain, 2 = producer
    const int lane = tid & 31;

    __shared__ __align__(16) float sb0[NS], sb1[NS];
    __shared__ __align__(8)  float pe_ring[8][NS];
    __shared__ float red[2];

    if (write_trans && bb < NS && tid < NS) {
        out[BB + bb * NS + tid] = trans[bb * NS + tid];
    }

    const int len  = lens[b];
    const int last = (len - 1) > 0 ? (len - 1) : 0;

    const int* tg = tags + (size_t)b * TT;
    const float* in_b = inputs + (size_t)b * TT * NS;
    const float2* in2 = (const float2*)in_b;

    float seq_score = 0.f;
    float s_cur = 0.f;
    int Mk = 0;
    unsigned long long e2[NS / 2];

    if (tid < NS) {
        // ---------------- sequence score (chain warps) ----------------
        float sc = 0.f;
        for (int t = j; t < TT; t += NS) {
            if (t < len) {
                int yt = tg[t];
                sc += __ldg(&in_b[(size_t)t * NS + yt]);
                if (t >= 1) sc += __ldg(&trans[tg[t - 1] * NS + yt]);
            }
        }
        #pragma unroll
        for (int o = 16; o; o >>= 1) sc += __shfl_xor_sync(0xffffffffu, sc, o);
        if (lane == 0) red[w] = sc;
    } else {
        // ---------------- producer: prefill pe ring for t = 1..6 ----------------
        #pragma unroll
        for (int t = 1; t <= 6; ++t) {
            if (t <= last) {
                const float2 em = __ldg(&in2[(size_t)t * 32 + lane]);
                float2* dst = (float2*)pe_ring[t & 7];
                dst[lane] = make_float2(__expf(em.x), __expf(em.y));
            }
        }
    }
    __syncthreads();
    if (tid < NS) {
        seq_score = red[0] + red[1];

        // ---------------- E column j, packed f32x2 pairs over i ----------------
        #pragma unroll
        for (int k = 0; k < NS / 2; ++k) {
            unsigned lo = __float_as_uint(__expf(__ldg(&trans[(2 * k) * NS + j])));
            unsigned hi = __float_as_uint(__expf(__ldg(&trans[(2 * k + 1) * NS + j])));
            asm("mov.b64 %0, {%1, %2};" : "=l"(e2[k]) : "r"(lo), "r"(hi));
        }

        // s_j(t) = exp(alpha_j(t)) * 2^{-Mk_t}; renorm by exact power of two
        s_cur = __expf(in_b[j]);
        sb0[j] = s_cur;
    }

#define CSTEP(SRC, DST, T)                                                    \
    do {                                                                      \
        const unsigned s0b = __float_as_uint((SRC)[0]);                       \
        const unsigned ke  = s0b >> 23;                                       \
        Mk += (int)ke - 127;                                                  \
        const float r_inv = __uint_as_float((254u - ke) << 23);               \
        const float f = pe_ring[(T) & 7][j] * r_inv;                          \
        const ulonglong2* p4 = (const ulonglong2*)(SRC);                      \
        unsigned long long a0, a1, a2, a3, a4, a5, a6, a7;                    \
        {                                                                     \
            const ulonglong2 va = p4[0];                                      \
            const ulonglong2 vb = p4[1];                                      \
            const ulonglong2 vc = p4[2];                                      \
            const ulonglong2 vd = p4[3];                                      \
            MUL2(a0, va.x, e2[0]); MUL2(a1, va.y, e2[1]);                     \
            MUL2(a2, vb.x, e2[2]); MUL2(a3, vb.y, e2[3]);                     \
            MUL2(a4, vc.x, e2[4]); MUL2(a5, vc.y, e2[5]);                     \
            MUL2(a6, vd.x, e2[6]); MUL2(a7, vd.y, e2[7]);                     \
        }                                                                     \
        _Pragma("unroll")                                                     \
        for (int m = 1; m < 4; ++m) {                                         \
            const ulonglong2 va = p4[4 * m + 0];                              \
            const ulonglong2 vb = p4[4 * m + 1];                              \
            const ulonglong2 vc = p4[4 * m + 2];                              \
            const ulonglong2 vd = p4[4 * m + 3];                              \
            FMA2(a0, va.x, e2[8 * m + 0]); FMA2(a1, va.y, e2[8 * m + 1]);     \
            FMA2(a2, vb.x, e2[8 * m + 2]); FMA2(a3, vb.y, e2[8 * m + 3]);     \
            FMA2(a4, vc.x, e2[8 * m + 4]); FMA2(a5, vc.y, e2[8 * m + 5]);     \
            FMA2(a6, vd.x, e2[8 * m + 6]); FMA2(a7, vd.y, e2[8 * m + 7]);     \
        }                                                                     \
        ADD2(a0, a0, a1); ADD2(a2, a2, a3);                                   \
        ADD2(a4, a4, a5); ADD2(a6, a6, a7);                                   \
        ADD2(a0, a0, a2); ADD2(a4, a4, a6);                                   \
        ADD2(a0, a0, a4);                                                     \
        unsigned lo_, hi_;                                                    \
        UNPACK2(lo_, hi_, a0);                                                \
        const float acc = __uint_as_float(lo_) + __uint_as_float(hi_);        \
        s_cur = acc * f;                                                      \
        (DST)[j] = s_cur;                                                     \
    } while (0)

#define PSTEP(T)                                                              \
    do {                                                                      \
        const int tp = (T) + 6;                                               \
        if (tp <= last) {                                                     \
            const float2 em = __ldg(&in2[(size_t)tp * 32 + lane]);            \
            float2* dst = (float2*)pe_ring[tp & 7];                           \
            dst[lane] = make_float2(__expf(em.x), __expf(em.y));              \
        }                                                                     \
    } while (0)

    int t = 1;
    for (; t + 1 <= last; t += 2) {
        __syncthreads();
        if (tid < NS) CSTEP(sb0, sb1, t); else PSTEP(t);
        __syncthreads();
        if (tid < NS) CSTEP(sb1, sb0, t + 1); else PSTEP(t + 1);
    }
    if (t <= last) {
        __syncthreads();
        if (tid < NS) CSTEP(sb0, sb1, t); else PSTEP(t);
    }
#undef CSTEP
#undef PSTEP

    // ---------------- final logsumexp over states (chain warps) ----------------
    const float alpha = (tid < NS)
        ? (__logf(s_cur) + (float)Mk * 0.6931471805599453f) : -1e30f;

    float mx = alpha;
    #pragma unroll
    for (int o = 16; o; o >>= 1)
        mx = fmaxf(mx, __shfl_xor_sync(0xffffffffu, mx, o));
    if (lane == 0 && w < 2) red[w] = mx;
    __syncthreads();
    mx = fmaxf(red[0], red[1]);
    __syncthreads();

    float s = (tid < NS) ? __expf(alpha - mx) : 0.f;
    #pragma unroll
    for (int o = 16; o; o >>= 1)
        s += __shfl_xor_sync(0xffffffffu, s, o);
    if (lane == 0 && w < 2) red[w] = s;
    __syncthreads();
    s = red[0] + red[1];

    if (tid == 0) out[b] = seq_score - (mx + __logf(s));
}

extern "C" void kernel_launch(void* const* d_in, const int* in_sizes, int n_in,
                              void* d_out, int out_size) {
    const float* inputs = (const float*)d_in[0];   // [B,T,N] f32
    const float* trans  = (const float*)d_in[1];   // [N,N]   f32
    const int*   tags   = (const int*)d_in[2];     // [B,T]   i32
    const int*   lens   = (const int*)d_in[3];     // [B]     i32
    float* out = (float*)d_out;

    const int write_trans = (out_size >= BB + NS * NS) ? 1 : 0;
    rank_kernel<<<1, BB>>>(lens);
    crf_kernel<<<BB, 96>>>(inputs, trans, tags, lens, out, write_trans);
}

// round 9
// speedup vs baseline: 1.8044x; 1.8044x over previous
#include <cuda_runtime.h>

#define BB 512
#define TT 512
#define NS 64

// sm_103a packed fp32 pipe: 2 full-precision fp32 FMAs / MULs / ADDs per instr
#define FMA2(acc, p, e) \
    asm("fma.rn.f32x2 %0, %1, %2, %0;" : "+l"(acc) : "l"(p), "l"(e))
#define MUL2(out, a, b) \
    asm("mul.rn.f32x2 %0, %1, %2;" : "=l"(out) : "l"(a), "l"(b))
#define ADD2(out, a, b) \
    asm("add.rn.f32x2 %0, %1, %2;" : "=l"(out) : "l"(a), "l"(b))
#define UNPACK2(lo, hi, v) \
    asm("mov.b64 {%0, %1}, %2;" : "=r"(lo), "=r"(hi) : "l"(v))

__device__ int      d_perm[BB];
__device__ float    d_meet[2][BB][NS];   // meeting vectors (fwd / bwd)
__device__ float    d_seq[BB];
__device__ int      d_mk[2][BB];
__device__ unsigned d_flag[BB];

// Rank batches by length (descending) + zero rendezvous flags each replay.
__global__ void rank_kernel(const int* __restrict__ lens) {
    __shared__ int L[BB];
    const int b = threadIdx.x;
    L[b] = lens[b];
    d_flag[b] = 0u;
    __syncthreads();
    const int myl = L[b];
    int r = 0;
    #pragma unroll 8
    for (int i = 0; i < BB; ++i) {
        const int li = L[i];
        r += (li > myl) || (li == myl && i < b);
    }
    d_perm[r] = b;
}

// Block 2r = forward half-chain of batch perm[r], block 2r+1 = backward
// half-chain. Each block: 128 threads launched, only one warp-pair (selected
// by (bid>>2)&1 to spread across SMSPs) survives; thread j owns state j and
// does the full 64-wide FMA2 dot (R7 structure). Halves rendezvous via
// __device__ scratch; the second finisher combines and writes out[b].
__global__ __launch_bounds__(128) void crf_kernel(
    const float* __restrict__ inputs,   // [B,T,N]
    const float* __restrict__ trans,    // [N,N]
    const int*   __restrict__ tags,    // [B,T]
    const int*   __restrict__ lens,    // [B]
    float*       __restrict__ out,     // [B] ll, then [N*N] trans copy
    int write_trans)
{
    const int bid = blockIdx.x;
    const int pi  = bid >> 1;     // sorted rank
    const int dir = bid & 1;      // 0 = forward, 1 = backward
    const int b   = d_perm[pi];
    const int sel = (bid >> 2) & 1;
    const int tid = threadIdx.x;

    if (write_trans && bid < 32) {
        out[BB + bid * 128 + tid] = trans[bid * 128 + tid];
    }
    if ((tid >> 6) != sel) return;   // unused warp-pair exits before barriers

    const int j    = tid & 63;      // owned state
    const int w    = (tid >> 5) & 1;
    const int lane = tid & 31;

    __shared__ __align__(16) float sb0[NS], sb1[NS];
    __shared__ float red[2];
    __shared__ unsigned oldf;

    const int len  = lens[b];
    const int last = (len - 1) > 0 ? (len - 1) : 0;
    const int mid  = last >> 1;

    const float* in_b = inputs + (size_t)b * TT * NS;

    float seq_score = 0.f;
    if (dir == 0) {
        // ---------------- sequence score (forward block only) ----------------
        const int* tg = tags + (size_t)b * TT;
        float sc = 0.f;
        for (int t = j; t < TT; t += NS) {
            if (t < len) {
                int yt = tg[t];
                sc += __ldg(&in_b[(size_t)t * NS + yt]);
                if (t >= 1) sc += __ldg(&trans[tg[t - 1] * NS + yt]);
            }
        }
        #pragma unroll
        for (int o = 16; o; o >>= 1) sc += __shfl_xor_sync(0xffffffffu, sc, o);
        if (lane == 0) red[w] = sc;
        __syncthreads();
        seq_score = red[0] + red[1];
        __syncthreads();
    }

    // ---- E vector: forward = column j (stride NS), backward = row j ----
    unsigned long long e2[NS / 2];
    if (dir == 0) {
        #pragma unroll
        for (int k = 0; k < NS / 2; ++k) {
            unsigned lo = __float_as_uint(__expf(__ldg(&trans[(2 * k) * NS + j])));
            unsigned hi = __float_as_uint(__expf(__ldg(&trans[(2 * k + 1) * NS + j])));
            asm("mov.b64 %0, {%1, %2};" : "=l"(e2[k]) : "r"(lo), "r"(hi));
        }
    } else {
        #pragma unroll
        for (int k = 0; k < NS / 2; ++k) {
            unsigned lo = __float_as_uint(__expf(__ldg(&trans[j * NS + 2 * k])));
            unsigned hi = __float_as_uint(__expf(__ldg(&trans[j * NS + 2 * k + 1])));
            asm("mov.b64 %0, {%1, %2};" : "=l"(e2[k]) : "r"(lo), "r"(hi));
        }
    }

    int Mk = 0;
    float s_cur;

#define STEP(SRC, DST, PE)                                                    \
    do {                                                                      \
        __syncthreads();                                                      \
        const unsigned s0b = __float_as_uint((SRC)[0]);                       \
        const unsigned ke  = s0b >> 23;                                       \
        Mk += (int)ke - 127;                                                  \
        const float r_inv = __uint_as_float((254u - ke) << 23);               \
        const float f = (PE) * r_inv;                                         \
        const ulonglong2* p4 = (const ulonglong2*)(SRC);                      \
        unsigned long long a0, a1, a2, a3, a4, a5, a6, a7;                    \
        {                                                                     \
            const ulonglong2 va = p4[0];                                      \
            const ulonglong2 vb = p4[1];                                      \
            const ulonglong2 vc = p4[2];                                      \
            const ulonglong2 vd = p4[3];                                      \
            MUL2(a0, va.x, e2[0]); MUL2(a1, va.y, e2[1]);                     \
            MUL2(a2, vb.x, e2[2]); MUL2(a3, vb.y, e2[3]);                     \
            MUL2(a4, vc.x, e2[4]); MUL2(a5, vc.y, e2[5]);                     \
            MUL2(a6, vd.x, e2[6]); MUL2(a7, vd.y, e2[7]);                     \
        }                                                                     \
        _Pragma("unroll")                                                     \
        for (int m = 1; m < 4; ++m) {                                         \
            const ulonglong2 va = p4[4 * m + 0];                              \
            const ulonglong2 vb = p4[4 * m + 1];                              \
            const ulonglong2 vc = p4[4 * m + 2];                              \
            const ulonglong2 vd = p4[4 * m + 3];                              \
            FMA2(a0, va.x, e2[8 * m + 0]); FMA2(a1, va.y, e2[8 * m + 1]);     \
            FMA2(a2, vb.x, e2[8 * m + 2]); FMA2(a3, vb.y, e2[8 * m + 3]);     \
            FMA2(a4, vc.x, e2[8 * m + 4]); FMA2(a5, vc.y, e2[8 * m + 5]);     \
            FMA2(a6, vd.x, e2[8 * m + 6]); FMA2(a7, vd.y, e2[8 * m + 7]);     \
        }                                                                     \
        ADD2(a0, a0, a1); ADD2(a2, a2, a3);                                   \
        ADD2(a4, a4, a5); ADD2(a6, a6, a7);                                   \
        ADD2(a0, a0, a2); ADD2(a4, a4, a6);                                   \
        ADD2(a0, a0, a4);                                                     \
        unsigned lo_, hi_;                                                    \
        UNPACK2(lo_, hi_, a0);                                                \
        const float acc = __uint_as_float(lo_) + __uint_as_float(hi_);        \
        s_cur = acc * f;                                                      \
        (DST)[j] = s_cur;                                                     \
    } while (0)

    if (dir == 0) {
        // -------- forward: alpha over t = 0..mid (emits 0..mid) --------
        s_cur = __expf(in_b[j]);
        sb0[j] = s_cur;
        #define PEF(X) (((X) <= mid) ? __expf(__ldg(&in_b[(size_t)(X) * NS + j])) : 1.f)
        float pe0 = PEF(1), pe1 = PEF(2), pe2 = PEF(3);
        float pe3 = PEF(4), pe4 = PEF(5), pe5 = PEF(6);
        int t = 1;
        for (; t + 1 <= mid; t += 2) {
            STEP(sb0, sb1, pe0);
            STEP(sb1, sb0, pe1);
            pe0 = pe2; pe1 = pe3; pe2 = pe4; pe3 = pe5;
            pe4 = PEF(t + 6);
            pe5 = PEF(t + 7);
        }
        if (t <= mid) STEP(sb0, sb1, pe0);
        #undef PEF
    } else {
        // -------- backward: beta from t = last down to mid --------
        // smem holds w = pe .* beta (pe folded at store); final step uses
        // pe = 1 so beta(mid) excludes emit[mid] (it lives in alpha(mid)).
        s_cur = (last > mid) ? __expf(__ldg(&in_b[(size_t)last * NS + j])) : 1.f;
        sb0[j] = s_cur;
        #define PEB(X) (((X) > mid) ? __expf(__ldg(&in_b[(size_t)(X) * NS + j])) : 1.f)
        float pe0 = PEB(last - 1), pe1 = PEB(last - 2), pe2 = PEB(last - 3);
        float pe3 = PEB(last - 4), pe4 = PEB(last - 5), pe5 = PEB(last - 6);
        int p = last - 1;
        for (; p - 1 >= mid; p -= 2) {
            STEP(sb0, sb1, pe0);
            STEP(sb1, sb0, pe1);
            pe0 = pe2; pe1 = pe3; pe2 = pe4; pe3 = pe5;
            pe4 = PEB(p - 6);
            pe5 = PEB(p - 7);
        }
        if (p >= mid) STEP(sb0, sb1, pe0);
        #undef PEB
    }
#undef STEP

    // ---------------- rendezvous ----------------
    d_meet[dir][b][j] = s_cur;
    if (j == 0) {
        d_mk[dir][b] = Mk;
        if (dir == 0) d_seq[b] = seq_score;
    }
    __threadfence();
    __syncthreads();
    if (j == 0) oldf = atomicAdd(&d_flag[b], 1u);
    __syncthreads();

    if (oldf == 1u) {   // second finisher combines
        __threadfence();
        const float other = ((volatile float*)d_meet[dir ^ 1][b])[j];
        const int   mko   = ((volatile int*)d_mk[dir ^ 1])[b];
        const float seq   = dir ? ((volatile float*)d_seq)[b] : seq_score;

        float prod = s_cur * other;          // all terms positive
        #pragma unroll
        for (int o = 16; o; o >>= 1)
            prod += __shfl_xor_sync(0xffffffffu, prod, o);
        if (lane == 0) red[w] = prod;
        __syncthreads();
        const float Zs = red[0] + red[1];
        if (j == 0) {
            out[b] = seq - (__logf(Zs)
                     + (float)(Mk + mko) * 0.6931471805599453f);
        }
    }
}

extern "C" void kernel_launch(void* const* d_in, const int* in_sizes, int n_in,
                              void* d_out, int out_size) {
    const float* inputs = (const float*)d_in[0];   // [B,T,N] f32
    const float* trans  = (const float*)d_in[1];   // [N,N]   f32
    const int*   tags   = (const int*)d_in[2];     // [B,T]   i32
    const int*   lens   = (const int*)d_in[3];     // [B]     i32
    float* out = (float*)d_out;

    const int write_trans = (out_size >= BB + NS * NS) ? 1 : 0;
    rank_kernel<<<1, BB>>>(lens);
    crf_kernel<<<2 * BB, 128>>>(inputs, trans, tags, lens, out, write_trans);
}